// round 10
// baseline (speedup 1.0000x reference)
#include <cuda_runtime.h>
#include <cuda_bf16.h>
#include <cuda_fp16.h>
#include <cstdint>
#include <math.h>

#define B_  4
#define T_  2048
#define C_  1024
#define NH_ 16
#define HD_ 64
#define M_  (B_*T_)          // 8192 tokens
#define PQ_ 72               // padded row length (144B) for q/k prepack

// ---------------- scratch (static device globals; no runtime alloc) --------
__device__ __align__(256) float   g_qkv [(size_t)M_ * 3 * C_];
__device__ __align__(256) __half  g_xf  [(size_t)M_ * C_];
__device__ __align__(256) __half  g_wthf[(size_t)3 * C_ * C_];   // W_attn^T hi [3C, C]
__device__ __align__(256) __half  g_wtlf[(size_t)3 * C_ * C_];   // W_attn^T lo
__device__ __align__(256) __half  g_wpthf[(size_t)C_ * C_];      // W_proj^T hi
__device__ __align__(256) __half  g_wptlf[(size_t)C_ * C_];      // W_proj^T lo
__device__ __align__(256) __half  g_yf  [(size_t)M_ * C_];       // attn out fp16
__device__ __align__(256) __half  g_qpf [(size_t)B_*NH_*T_*PQ_];
__device__ __align__(256) __half  g_kpf [(size_t)B_*NH_*T_*PQ_];
__device__ __align__(256) __half  g_vtf [(size_t)B_*NH_*HD_*T_];

// ---------------- helpers ---------------------------------------------------
__device__ __forceinline__ uint32_t smem_u32(const void* p) {
    uint32_t a;
    asm("{ .reg .u64 t; cvta.to.shared.u64 t, %1; cvt.u32.u64 %0, t; }" : "=r"(a) : "l"(p));
    return a;
}

#define LDSM_X4(r0, r1, r2, r3, addr) \
    asm volatile("ldmatrix.sync.aligned.m8n8.x4.shared.b16 {%0,%1,%2,%3}, [%4];" \
        : "=r"(r0), "=r"(r1), "=r"(r2), "=r"(r3) : "r"(addr))

#define CP_ASYNC16(dst, src) \
    asm volatile("cp.async.cg.shared.global [%0], [%1], 16;" :: "r"(dst), "l"(src))
#define CP_COMMIT() asm volatile("cp.async.commit_group;" ::: "memory")
#define CP_WAIT(n)  asm volatile("cp.async.wait_group %0;" :: "n"(n) : "memory")

// fp16 MMA
__device__ __forceinline__ void mma16816h(float* d, const uint32_t* a,
                                          uint32_t b0, uint32_t b1) {
    asm("mma.sync.aligned.m16n8k16.row.col.f32.f16.f16.f32 "
        "{%0,%1,%2,%3}, {%4,%5,%6,%7}, {%8,%9}, {%0,%1,%2,%3};"
        : "+f"(d[0]), "+f"(d[1]), "+f"(d[2]), "+f"(d[3])
        : "r"(a[0]), "r"(a[1]), "r"(a[2]), "r"(a[3]), "r"(b0), "r"(b1));
}

__device__ __forceinline__ uint32_t pack_f16(float a, float b) {
    uint32_t r;
    asm("cvt.rn.f16x2.f32 %0, %1, %2;" : "=r"(r) : "f"(b), "f"(a));  // lo16 = a
    return r;
}

__device__ __forceinline__ float ex2f(float x) {
    float r; asm("ex2.approx.f32 %0, %1;" : "=f"(r) : "f"(x)); return r;
}

// ---------------- conversion kernels ----------------------------------------
__global__ __launch_bounds__(256)
void convert_f16(const float* __restrict__ in, __half* __restrict__ out, int n)
{
    int i = (blockIdx.x * 256 + threadIdx.x) * 4;
    if (i >= n) return;
    float4 v = *(const float4*)(in + i);
    uint32_t p0 = pack_f16(v.x, v.y);
    uint32_t p1 = pack_f16(v.z, v.w);
    *(uint2*)(out + i) = make_uint2(p0, p1);
}

// W [K,N] fp32 -> Wt hi/lo fp16 [N,K] (transpose + 2-term split)
__global__ __launch_bounds__(256)
void transpose_convert_f16(const float* __restrict__ W, __half* __restrict__ Thi,
                           __half* __restrict__ Tlo, int K, int N)
{
    __shared__ float t[32][33];
    int n0 = blockIdx.x * 32, k0 = blockIdx.y * 32;
    int tx = threadIdx.x & 31, ty = threadIdx.x >> 5;
    #pragma unroll
    for (int i = 0; i < 32; i += 8)
        t[ty + i][tx] = W[(size_t)(k0 + ty + i) * N + n0 + tx];
    __syncthreads();
    #pragma unroll
    for (int i = 0; i < 32; i += 8) {
        float v = t[tx][ty + i];
        size_t o = (size_t)(n0 + ty + i) * K + k0 + tx;
        __half h = __float2half_rn(v);
        Thi[o] = h;
        Tlo[o] = __float2half_rn(v - __half2float(h));
    }
}

// split qkv fp32 -> fp16 attention layouts. q pre-scaled by 0.125*log2(e).
__global__ __launch_bounds__(256)
void qkv_split(const float* __restrict__ qkv,
               __half* __restrict__ qf, __half* __restrict__ kf,
               __half* __restrict__ vf)
{
    __shared__ float vt[64][65];
    const int t0 = blockIdx.x * 64, h = blockIdx.y, b = blockIdx.z;
    const int bh = b * NH_ + h;
    const int tid = threadIdx.x;
    const int tok = tid >> 2, dseg = (tid & 3) << 4;
    const float cs = 0.125f * 1.44269504089f;

    const float* src = qkv + (size_t)(b * T_ + t0 + tok) * (3 * C_) + h * HD_ + dseg;

    #pragma unroll
    for (int which = 0; which < 2; which++) {
        const float* s = src + which * C_;
        const float sc = which ? 1.0f : cs;
        __half* d = (which ? kf : qf) + (size_t)(bh * T_ + t0 + tok) * PQ_ + dseg;
        #pragma unroll
        for (int i = 0; i < 2; i++) {
            float4 va = *(const float4*)(s + i * 8);
            float4 vb = *(const float4*)(s + i * 8 + 4);
            uint32_t p0 = pack_f16(va.x * sc, va.y * sc);
            uint32_t p1 = pack_f16(va.z * sc, va.w * sc);
            uint32_t p2 = pack_f16(vb.x * sc, vb.y * sc);
            uint32_t p3 = pack_f16(vb.z * sc, vb.w * sc);
            *(uint4*)(d + i * 8) = make_uint4(p0, p1, p2, p3);
        }
    }

    {
        const float* s = src + 2 * C_;
        #pragma unroll
        for (int i = 0; i < 4; i++) {
            float4 v = *(const float4*)(s + i * 4);
            vt[tok][dseg + i*4 + 0] = v.x; vt[tok][dseg + i*4 + 1] = v.y;
            vt[tok][dseg + i*4 + 2] = v.z; vt[tok][dseg + i*4 + 3] = v.w;
        }
    }
    __syncthreads();
    {
        const int d = tid >> 2, tseg = (tid & 3) << 4;
        __half* dst = vf + ((size_t)bh * HD_ + d) * T_ + t0 + tseg;
        #pragma unroll
        for (int i = 0; i < 2; i++) {
            uint32_t p0 = pack_f16(vt[tseg+i*8+0][d], vt[tseg+i*8+1][d]);
            uint32_t p1 = pack_f16(vt[tseg+i*8+2][d], vt[tseg+i*8+3][d]);
            uint32_t p2 = pack_f16(vt[tseg+i*8+4][d], vt[tseg+i*8+5][d]);
            uint32_t p3 = pack_f16(vt[tseg+i*8+6][d], vt[tseg+i*8+7][d]);
            *(uint4*)(dst + i * 8) = make_uint4(p0, p1, p2, p3);
        }
    }
}

// ---------------- pipelined mma.sync GEMM -----------------------------------
// C[M,N] = Af[M,K] @ (Bhi+Blo)[N,K]^T + bias.  A single fp16, B 2-term fp16.
// 2 MMAs per fragment. 128x128 CTA, 8 warps, k-chunk 32, 2-stage cp.async.
#define ASTR 80
#define GSTG 30720                 // 3 arrays x 128 x 80
#define SM_A  0
#define SM_BH 10240
#define SM_BL 20480
#define SM_BIAS (2 * GSTG)
#define GEMM_SMEM (2 * GSTG + 512)

__global__ __launch_bounds__(256, 2)
void gemm_mma_kernel(const __half* __restrict__ Af,
                     const __half* __restrict__ Bhi, const __half* __restrict__ Blo,
                     const float* __restrict__ bias, float* __restrict__ Cout,
                     int M, int N, int K)
{
    extern __shared__ __align__(16) char sm[];
    float* sbias = (float*)(sm + SM_BIAS);
    const uint32_t smb = smem_u32(sm);

    const int tid  = threadIdx.x;
    const int wid  = tid >> 5;
    const int lane = tid & 31;
    const int mw   = wid & 3;
    const int nw   = wid >> 2;
    const int row0 = blockIdx.y * 128;
    const int col0 = blockIdx.x * 128;

    if (tid < 128) sbias[tid] = bias[col0 + tid];

    float acc[2][8][4];
    #pragma unroll
    for (int i = 0; i < 2; i++)
        #pragma unroll
        for (int j = 0; j < 8; j++)
            #pragma unroll
            for (int q = 0; q < 4; q++) acc[i][j][q] = 0.f;

    const int sr0 = tid >> 2;          // 0..63
    const int ssg = tid & 3;           // 16B granule
    const int lr = lane & 15;
    const int lc = lane >> 4;
    const int NC = K >> 5;

    auto load_stage = [&](int kc, int stg) {
        const uint32_t sb = smb + stg * GSTG;
        #pragma unroll
        for (int it = 0; it < 2; it++) {
            int r = sr0 + it * 64;
            uint32_t so = (uint32_t)(r * ASTR + ssg * 16);
            size_t ga = (size_t)(row0 + r) * K + (kc << 5) + ssg * 8;
            size_t gb = (size_t)(col0 + r) * K + (kc << 5) + ssg * 8;
            CP_ASYNC16(sb + SM_A  + so, (const char*)(Af  + ga));
            CP_ASYNC16(sb + SM_BH + so, (const char*)(Bhi + gb));
            CP_ASYNC16(sb + SM_BL + so, (const char*)(Blo + gb));
        }
        CP_COMMIT();
    };

    load_stage(0, 0);

    for (int kc = 0; kc < NC; kc++) {
        const int stg = kc & 1;
        if (kc + 1 < NC) {
            load_stage(kc + 1, stg ^ 1);
            CP_WAIT(1);
        } else {
            CP_WAIT(0);
        }
        __syncthreads();

        const uint32_t sb = smb + stg * GSTG;
        #pragma unroll
        for (int ks = 0; ks < 2; ks++) {
            const uint32_t kb = (uint32_t)(lc * 16 + ks * 32);

            uint32_t af[2][4];
            #pragma unroll
            for (int mf = 0; mf < 2; mf++) {
                uint32_t ao = sb + SM_A + (uint32_t)((mw * 32 + mf * 16 + lr) * ASTR) + kb;
                LDSM_X4(af[mf][0], af[mf][1], af[mf][2], af[mf][3], ao);
            }

            #pragma unroll
            for (int np = 0; np < 4; np++) {
                uint32_t bo = sb + (uint32_t)((nw * 64 + np * 16 + lr) * ASTR) + kb;
                uint32_t bh0, bh1, bh2, bh3, bl0, bl1, bl2, bl3;
                LDSM_X4(bh0, bh1, bh2, bh3, bo + SM_BH);
                LDSM_X4(bl0, bl1, bl2, bl3, bo + SM_BL);
                mma16816h(acc[0][np * 2 + 0], af[0], bh0, bh2);
                mma16816h(acc[0][np * 2 + 1], af[0], bh1, bh3);
                mma16816h(acc[1][np * 2 + 0], af[1], bh0, bh2);
                mma16816h(acc[1][np * 2 + 1], af[1], bh1, bh3);
                mma16816h(acc[0][np * 2 + 0], af[0], bl0, bl2);
                mma16816h(acc[0][np * 2 + 1], af[0], bl1, bl3);
                mma16816h(acc[1][np * 2 + 0], af[1], bl0, bl2);
                mma16816h(acc[1][np * 2 + 1], af[1], bl1, bl3);
            }
        }
        __syncthreads();
    }

    #pragma unroll
    for (int mf = 0; mf < 2; mf++) {
        int r_ = row0 + mw * 32 + mf * 16 + (lane >> 2);
        #pragma unroll
        for (int nf = 0; nf < 8; nf++) {
            int cl = nw * 64 + nf * 8 + (lane & 3) * 2;
            float b0 = sbias[cl], b1 = sbias[cl + 1];
            float2 v0 = {acc[mf][nf][0] + b0, acc[mf][nf][1] + b1};
            float2 v1 = {acc[mf][nf][2] + b0, acc[mf][nf][3] + b1};
            *(float2*)(Cout + (size_t)r_ * N + col0 + cl) = v0;
            *(float2*)(Cout + (size_t)(r_ + 8) * N + col0 + cl) = v1;
        }
    }
}

// ---------------- fp16 tensor-core flash attention (R9, epilogue -> fp16) ---
#define AT_STR 144
#define SQ_F 0
#define AST_BASE 18432
#define AST_SIZE 18432
#define AST_K 0
#define AST_V 9216
#define ATTN_SMEM (AST_BASE + 2 * AST_SIZE)   // 55296

__global__ __launch_bounds__(256, 2)
void attn_mma_kernel(const __half* __restrict__ qf, const __half* __restrict__ kf,
                     const __half* __restrict__ vf, __half* __restrict__ yf)
{
    extern __shared__ char sm[];
    const uint32_t smb = smem_u32(sm);
    const int tid = threadIdx.x, lane = tid & 31, wid = tid >> 5;
    const int qb = (int)(gridDim.x - 1 - blockIdx.x);
    const int h  = blockIdx.y, b = blockIdx.z;
    const int bh = b * NH_ + h;

    {
        const int row = tid >> 1, g0 = (tid & 1) * 4;
        const size_t gbase = ((size_t)bh * T_ + qb * 128 + row) * PQ_ + g0 * 8;
        const uint32_t sbase = smb + SQ_F + (uint32_t)(row * AT_STR) + g0 * 16;
        #pragma unroll
        for (int g = 0; g < 4; g++)
            CP_ASYNC16(sbase + g * 16, (const char*)(qf + gbase + g * 8));
        CP_COMMIT();
    }

    const int srow = tid >> 2;
    const int sg   = (tid & 3) * 2;

    auto load_stage = [&](int kt, int stg) {
        const uint32_t sb = smb + AST_BASE + stg * AST_SIZE;
        const uint32_t so = (uint32_t)(srow * AT_STR + sg * 16);
        const size_t gk = ((size_t)bh * T_ + kt * 64 + srow) * PQ_ + sg * 8;
        const size_t gv = ((size_t)bh * HD_ + srow) * T_ + kt * 64 + sg * 8;
        CP_ASYNC16(sb + AST_K + so,      (const char*)(kf + gk));
        CP_ASYNC16(sb + AST_K + so + 16, (const char*)(kf + gk + 8));
        CP_ASYNC16(sb + AST_V + so,      (const char*)(vf + gv));
        CP_ASYNC16(sb + AST_V + so + 16, (const char*)(vf + gv + 8));
        CP_COMMIT();
    };

    float m0 = -1e30f, m1 = -1e30f, lsum0 = 0.f, lsum1 = 0.f;
    float o[8][4];
    #pragma unroll
    for (int j = 0; j < 8; j++)
        #pragma unroll
        for (int q = 0; q < 4; q++) o[j][q] = 0.f;

    const int lr = lane & 15, lc = lane >> 4;
    const int rowg0 = qb * 128 + wid * 16 + (lane >> 2);
    const int ntiles = 2 * qb + 2;

    load_stage(0, 0);

    for (int kt = 0; kt < ntiles; kt++) {
        const int stg = kt & 1;
        if (kt + 1 < ntiles) {
            load_stage(kt + 1, stg ^ 1);
            CP_WAIT(1);
        } else {
            CP_WAIT(0);
        }
        __syncthreads();

        const uint32_t sb = smb + AST_BASE + stg * AST_SIZE;

        float s[8][4];
        #pragma unroll
        for (int j = 0; j < 8; j++)
            #pragma unroll
            for (int q = 0; q < 4; q++) s[j][q] = 0.f;

        #pragma unroll
        for (int ks = 0; ks < 4; ks++) {
            const uint32_t kb = (uint32_t)(lc * 16 + ks * 32);
            uint32_t aq[4];
            uint32_t ao = smb + SQ_F + (uint32_t)((wid * 16 + lr) * AT_STR) + kb;
            LDSM_X4(aq[0], aq[1], aq[2], aq[3], ao);
            #pragma unroll
            for (int np = 0; np < 4; np++) {
                uint32_t bo = sb + AST_K + (uint32_t)((np * 16 + lr) * AT_STR) + kb;
                uint32_t b0, b1, b2, b3;
                LDSM_X4(b0, b1, b2, b3, bo);
                mma16816h(s[np * 2 + 0], aq, b0, b2);
                mma16816h(s[np * 2 + 1], aq, b1, b3);
            }
        }

        if (kt >= 2 * qb) {
            const int colb = kt * 64 + 2 * (lane & 3);
            #pragma unroll
            for (int j = 0; j < 8; j++) {
                int c0 = colb + 8 * j;
                if (c0     > rowg0)     s[j][0] = -1e30f;
                if (c0 + 1 > rowg0)     s[j][1] = -1e30f;
                if (c0     > rowg0 + 8) s[j][2] = -1e30f;
                if (c0 + 1 > rowg0 + 8) s[j][3] = -1e30f;
            }
        }

        float mx0 = -1e30f, mx1 = -1e30f;
        #pragma unroll
        for (int j = 0; j < 8; j++) {
            mx0 = fmaxf(mx0, fmaxf(s[j][0], s[j][1]));
            mx1 = fmaxf(mx1, fmaxf(s[j][2], s[j][3]));
        }
        mx0 = fmaxf(mx0, __shfl_xor_sync(0xffffffffu, mx0, 1));
        mx0 = fmaxf(mx0, __shfl_xor_sync(0xffffffffu, mx0, 2));
        mx1 = fmaxf(mx1, __shfl_xor_sync(0xffffffffu, mx1, 1));
        mx1 = fmaxf(mx1, __shfl_xor_sync(0xffffffffu, mx1, 2));

        float mn0 = fmaxf(m0, mx0), mn1 = fmaxf(m1, mx1);
        float a0 = ex2f(m0 - mn0),  a1 = ex2f(m1 - mn1);
        m0 = mn0; m1 = mn1;

        float sum0 = 0.f, sum1 = 0.f;
        #pragma unroll
        for (int j = 0; j < 8; j++) {
            s[j][0] = ex2f(s[j][0] - mn0);
            s[j][1] = ex2f(s[j][1] - mn0);
            s[j][2] = ex2f(s[j][2] - mn1);
            s[j][3] = ex2f(s[j][3] - mn1);
            sum0 += s[j][0] + s[j][1];
            sum1 += s[j][2] + s[j][3];
        }
        sum0 += __shfl_xor_sync(0xffffffffu, sum0, 1);
        sum0 += __shfl_xor_sync(0xffffffffu, sum0, 2);
        sum1 += __shfl_xor_sync(0xffffffffu, sum1, 1);
        sum1 += __shfl_xor_sync(0xffffffffu, sum1, 2);
        lsum0 = lsum0 * a0 + sum0;
        lsum1 = lsum1 * a1 + sum1;

        #pragma unroll
        for (int j = 0; j < 8; j++) {
            o[j][0] *= a0; o[j][1] *= a0;
            o[j][2] *= a1; o[j][3] *= a1;
        }

        uint32_t pf[4][4];
        #pragma unroll
        for (int s2 = 0; s2 < 4; s2++) {
            pf[s2][0] = pack_f16(s[2*s2  ][0], s[2*s2  ][1]);
            pf[s2][1] = pack_f16(s[2*s2  ][2], s[2*s2  ][3]);
            pf[s2][2] = pack_f16(s[2*s2+1][0], s[2*s2+1][1]);
            pf[s2][3] = pack_f16(s[2*s2+1][2], s[2*s2+1][3]);
        }

        #pragma unroll
        for (int s2 = 0; s2 < 4; s2++) {
            const uint32_t kb = (uint32_t)(lc * 16 + s2 * 32);
            #pragma unroll
            for (int np = 0; np < 4; np++) {
                uint32_t bo = sb + AST_V + (uint32_t)((np * 16 + lr) * AT_STR) + kb;
                uint32_t b0, b1, b2, b3;
                LDSM_X4(b0, b1, b2, b3, bo);
                mma16816h(o[np * 2 + 0], pf[s2], b0, b2);
                mma16816h(o[np * 2 + 1], pf[s2], b1, b3);
            }
        }
        __syncthreads();
    }

    float inv0 = 1.f / lsum0, inv1 = 1.f / lsum1;
    const int tok0 = b * T_ + qb * 128 + wid * 16 + (lane >> 2);
    #pragma unroll
    for (int nf = 0; nf < 8; nf++) {
        int d = h * HD_ + nf * 8 + (lane & 3) * 2;
        *(uint32_t*)(yf + (size_t)tok0 * C_ + d)       = pack_f16(o[nf][0] * inv0, o[nf][1] * inv0);
        *(uint32_t*)(yf + (size_t)(tok0 + 8) * C_ + d) = pack_f16(o[nf][2] * inv1, o[nf][3] * inv1);
    }
}

// ---------------------------------------------------------------------------
extern "C" void kernel_launch(void* const* d_in, const int* in_sizes, int n_in,
                              void* d_out, int out_size)
{
    const float* x      = (const float*)d_in[0];
    const float* W_attn = (const float*)d_in[1];
    const float* b_attn = (const float*)d_in[2];
    const float* W_proj = (const float*)d_in[3];
    const float* b_proj = (const float*)d_in[4];
    float* out = (float*)d_out;

    float* qkv_ptr;
    __half *xf, *wthf, *wtlf, *wpthf, *wptlf, *yf, *qpf, *kpf, *vtf;
    cudaGetSymbolAddress((void**)&qkv_ptr, g_qkv);
    cudaGetSymbolAddress((void**)&xf,    g_xf);
    cudaGetSymbolAddress((void**)&wthf,  g_wthf);
    cudaGetSymbolAddress((void**)&wtlf,  g_wtlf);
    cudaGetSymbolAddress((void**)&wpthf, g_wpthf);
    cudaGetSymbolAddress((void**)&wptlf, g_wptlf);
    cudaGetSymbolAddress((void**)&yf,    g_yf);
    cudaGetSymbolAddress((void**)&qpf,   g_qpf);
    cudaGetSymbolAddress((void**)&kpf,   g_kpf);
    cudaGetSymbolAddress((void**)&vtf,   g_vtf);

    cudaFuncSetAttribute(gemm_mma_kernel,
                         cudaFuncAttributeMaxDynamicSharedMemorySize, GEMM_SMEM);
    cudaFuncSetAttribute(attn_mma_kernel,
                         cudaFuncAttributeMaxDynamicSharedMemorySize, ATTN_SMEM);

    // 1) conversions
    convert_f16<<<(M_ * C_) / 1024, 256>>>(x, xf, M_ * C_);
    transpose_convert_f16<<<dim3(3 * C_ / 32, C_ / 32), 256>>>(W_attn, wthf, wtlf, C_, 3 * C_);
    transpose_convert_f16<<<dim3(C_ / 32, C_ / 32), 256>>>(W_proj, wpthf, wptlf, C_, C_);

    // 2) qkv = x @ W_attn + b_attn   (fp16 A-single / B-2term, 2 MMAs)
    gemm_mma_kernel<<<dim3(3 * C_ / 128, M_ / 128), 256, GEMM_SMEM>>>(
        xf, wthf, wtlf, b_attn, qkv_ptr, M_, 3 * C_, C_);

    // 3) split qkv into fp16 attention operands
    qkv_split<<<dim3(T_ / 64, NH_, B_), 256>>>(qkv_ptr, qpf, kpf, vtf);

    // 4) fp16 flash attention -> yf
    attn_mma_kernel<<<dim3(T_ / 128, NH_, B_), 256, ATTN_SMEM>>>(qpf, kpf, vtf, yf);

    // 5) out = y @ W_proj + b_proj
    gemm_mma_kernel<<<dim3(C_ / 128, M_ / 128), 256, GEMM_SMEM>>>(
        yf, wpthf, wptlf, b_proj, out, M_, C_, C_);
}

// round 11
// speedup vs baseline: 1.1698x; 1.1698x over previous
#include <cuda_runtime.h>
#include <cuda_bf16.h>
#include <cuda_fp16.h>
#include <cstdint>
#include <math.h>

#define B_  4
#define T_  2048
#define C_  1024
#define NH_ 16
#define HD_ 64
#define M_  (B_*T_)          // 8192 tokens
#define PQ_ 72               // padded row length (144B) for q/k prepack

// ---------------- scratch (static device globals; no runtime alloc) --------
__device__ __align__(256) float          g_qkv [(size_t)M_ * 3 * C_];   // v region only used
__device__ __align__(256) __nv_bfloat16  g_xhi [(size_t)M_ * C_];
__device__ __align__(256) __nv_bfloat16  g_xlo [(size_t)M_ * C_];
__device__ __align__(256) __nv_bfloat16  g_wthi[(size_t)3 * C_ * C_];
__device__ __align__(256) __nv_bfloat16  g_wtlo[(size_t)3 * C_ * C_];
__device__ __align__(256) __nv_bfloat16  g_wpthi[(size_t)C_ * C_];
__device__ __align__(256) __nv_bfloat16  g_wptlo[(size_t)C_ * C_];
__device__ __align__(256) __nv_bfloat16  g_yhi [(size_t)M_ * C_];
__device__ __align__(256) __nv_bfloat16  g_ylo [(size_t)M_ * C_];
__device__ __align__(256) __half         g_qpf [(size_t)B_*NH_*T_*PQ_];
__device__ __align__(256) __half         g_kpf [(size_t)B_*NH_*T_*PQ_];
__device__ __align__(256) __half         g_vtf [(size_t)B_*NH_*HD_*T_];

// ---------------- helpers ---------------------------------------------------
__device__ __forceinline__ uint32_t smem_u32(const void* p) {
    uint32_t a;
    asm("{ .reg .u64 t; cvta.to.shared.u64 t, %1; cvt.u32.u64 %0, t; }" : "=r"(a) : "l"(p));
    return a;
}

#define LDSM_X4(r0, r1, r2, r3, addr) \
    asm volatile("ldmatrix.sync.aligned.m8n8.x4.shared.b16 {%0,%1,%2,%3}, [%4];" \
        : "=r"(r0), "=r"(r1), "=r"(r2), "=r"(r3) : "r"(addr))

#define CP_ASYNC16(dst, src) \
    asm volatile("cp.async.cg.shared.global [%0], [%1], 16;" :: "r"(dst), "l"(src))
#define CP_COMMIT() asm volatile("cp.async.commit_group;" ::: "memory")
#define CP_WAIT(n)  asm volatile("cp.async.wait_group %0;" :: "n"(n) : "memory")

// bf16 MMA (GEMMs)
__device__ __forceinline__ void mma16816(float* d, const uint32_t* a,
                                         uint32_t b0, uint32_t b1) {
    asm("mma.sync.aligned.m16n8k16.row.col.f32.bf16.bf16.f32 "
        "{%0,%1,%2,%3}, {%4,%5,%6,%7}, {%8,%9}, {%0,%1,%2,%3};"
        : "+f"(d[0]), "+f"(d[1]), "+f"(d[2]), "+f"(d[3])
        : "r"(a[0]), "r"(a[1]), "r"(a[2]), "r"(a[3]), "r"(b0), "r"(b1));
}

// fp16 MMA (attention)
__device__ __forceinline__ void mma16816h(float* d, const uint32_t* a,
                                          uint32_t b0, uint32_t b1) {
    asm("mma.sync.aligned.m16n8k16.row.col.f32.f16.f16.f32 "
        "{%0,%1,%2,%3}, {%4,%5,%6,%7}, {%8,%9}, {%0,%1,%2,%3};"
        : "+f"(d[0]), "+f"(d[1]), "+f"(d[2]), "+f"(d[3])
        : "r"(a[0]), "r"(a[1]), "r"(a[2]), "r"(a[3]), "r"(b0), "r"(b1));
}

__device__ __forceinline__ void pack_hilo(float a, float b, uint32_t& h, uint32_t& l) {
    asm("cvt.rn.bf16x2.f32 %0, %1, %2;" : "=r"(h) : "f"(b), "f"(a));
    float fa = __uint_as_float(h << 16);
    float fb = __uint_as_float(h & 0xffff0000u);
    asm("cvt.rn.bf16x2.f32 %0, %1, %2;" : "=r"(l) : "f"(b - fb), "f"(a - fa));
}

__device__ __forceinline__ uint32_t pack_f16(float a, float b) {
    uint32_t r;
    asm("cvt.rn.f16x2.f32 %0, %1, %2;" : "=r"(r) : "f"(b), "f"(a));  // lo16 = a
    return r;
}

__device__ __forceinline__ float ex2f(float x) {
    float r; asm("ex2.approx.f32 %0, %1;" : "=f"(r) : "f"(x)); return r;
}

// ---------------- conversion kernels ----------------------------------------
__global__ __launch_bounds__(256)
void convert_hilo(const float* __restrict__ in, __nv_bfloat16* __restrict__ hi,
                  __nv_bfloat16* __restrict__ lo, int n)
{
    int i = (blockIdx.x * 256 + threadIdx.x) * 4;
    if (i >= n) return;
    float4 v = *(const float4*)(in + i);
    uint32_t h0, l0, h1, l1;
    pack_hilo(v.x, v.y, h0, l0);
    pack_hilo(v.z, v.w, h1, l1);
    *(uint2*)(hi + i) = make_uint2(h0, h1);
    *(uint2*)(lo + i) = make_uint2(l0, l1);
}

__global__ __launch_bounds__(256)
void transpose_convert(const float* __restrict__ W, __nv_bfloat16* __restrict__ Thi,
                       __nv_bfloat16* __restrict__ Tlo, int K, int N)
{
    __shared__ float t[32][33];
    int n0 = blockIdx.x * 32, k0 = blockIdx.y * 32;
    int tx = threadIdx.x & 31, ty = threadIdx.x >> 5;
    #pragma unroll
    for (int i = 0; i < 32; i += 8)
        t[ty + i][tx] = W[(size_t)(k0 + ty + i) * N + n0 + tx];
    __syncthreads();
    #pragma unroll
    for (int i = 0; i < 32; i += 8) {
        float v = t[tx][ty + i];
        size_t o = (size_t)(n0 + ty + i) * K + k0 + tx;
        __nv_bfloat16 h = __float2bfloat16_rn(v);
        Thi[o] = h;
        Tlo[o] = __float2bfloat16_rn(v - __bfloat162float(h));
    }
}

// v-only split: fp32 qkv v-region -> transposed fp16 [bh, d, T]
__global__ __launch_bounds__(256)
void v_split(const float* __restrict__ qkv, __half* __restrict__ vf)
{
    __shared__ float vt[64][65];
    const int t0 = blockIdx.x * 64, h = blockIdx.y, b = blockIdx.z;
    const int bh = b * NH_ + h;
    const int tid = threadIdx.x;
    const int tok = tid >> 2, dseg = (tid & 3) << 4;

    const float* s = qkv + (size_t)(b * T_ + t0 + tok) * (3 * C_) + 2 * C_ + h * HD_ + dseg;
    #pragma unroll
    for (int i = 0; i < 4; i++) {
        float4 v = *(const float4*)(s + i * 4);
        vt[tok][dseg + i*4 + 0] = v.x; vt[tok][dseg + i*4 + 1] = v.y;
        vt[tok][dseg + i*4 + 2] = v.z; vt[tok][dseg + i*4 + 3] = v.w;
    }
    __syncthreads();
    {
        const int d = tid >> 2, tseg = (tid & 3) << 4;
        __half* dst = vf + ((size_t)bh * HD_ + d) * T_ + t0 + tseg;
        #pragma unroll
        for (int i = 0; i < 2; i++) {
            uint32_t p0 = pack_f16(vt[tseg+i*8+0][d], vt[tseg+i*8+1][d]);
            uint32_t p1 = pack_f16(vt[tseg+i*8+2][d], vt[tseg+i*8+3][d]);
            uint32_t p2 = pack_f16(vt[tseg+i*8+4][d], vt[tseg+i*8+5][d]);
            uint32_t p3 = pack_f16(vt[tseg+i*8+6][d], vt[tseg+i*8+7][d]);
            *(uint4*)(dst + i * 8) = make_uint4(p0, p1, p2, p3);
        }
    }
}

// ---------------- pipelined mma.sync GEMM (bf16 3-term, R9-proven) ----------
// MODE 0: plain fp32 C + bias (proj).  MODE 1: qkv — q/k cols write fused
// fp16 prepack (q scaled by cs); v cols write fp32 qkv.
#define ASTR 80
#define STG 40960
#define SM_AHI 0
#define SM_ALO 10240
#define SM_BHI 20480
#define SM_BLO 30720
#define SM_BIAS (2 * STG)
#define GEMM_SMEM (2 * STG + 512)

template<int MODE>
__global__ __launch_bounds__(256, 2)
void gemm_mma_kernel(const __nv_bfloat16* __restrict__ Ahi, const __nv_bfloat16* __restrict__ Alo,
                     const __nv_bfloat16* __restrict__ Bhi, const __nv_bfloat16* __restrict__ Blo,
                     const float* __restrict__ bias, float* __restrict__ Cout,
                     __half* __restrict__ qf, __half* __restrict__ kfp,
                     int M, int N, int K)
{
    extern __shared__ __align__(16) char sm[];
    float* sbias = (float*)(sm + SM_BIAS);
    const uint32_t smb = smem_u32(sm);

    const int tid  = threadIdx.x;
    const int wid  = tid >> 5;
    const int lane = tid & 31;
    const int mw   = wid & 3;
    const int nw   = wid >> 2;
    const int row0 = blockIdx.y * 128;
    const int col0 = blockIdx.x * 128;

    if (tid < 128) sbias[tid] = bias[col0 + tid];

    float acc[2][8][4];
    #pragma unroll
    for (int i = 0; i < 2; i++)
        #pragma unroll
        for (int j = 0; j < 8; j++)
            #pragma unroll
            for (int q = 0; q < 4; q++) acc[i][j][q] = 0.f;

    const int sr0 = tid >> 2;
    const int ssg = tid & 3;
    const int lr = lane & 15;
    const int lc = lane >> 4;
    const int NC = K >> 5;

    auto load_stage = [&](int kc, int stg) {
        const uint32_t sb = smb + stg * STG;
        #pragma unroll
        for (int it = 0; it < 2; it++) {
            int r = sr0 + it * 64;
            uint32_t so = (uint32_t)(r * ASTR + ssg * 16);
            size_t ga = (size_t)(row0 + r) * K + (kc << 5) + ssg * 8;
            size_t gb = (size_t)(col0 + r) * K + (kc << 5) + ssg * 8;
            CP_ASYNC16(sb + SM_AHI + so, (const char*)(Ahi + ga));
            CP_ASYNC16(sb + SM_ALO + so, (const char*)(Alo + ga));
            CP_ASYNC16(sb + SM_BHI + so, (const char*)(Bhi + gb));
            CP_ASYNC16(sb + SM_BLO + so, (const char*)(Blo + gb));
        }
        CP_COMMIT();
    };

    load_stage(0, 0);

    for (int kc = 0; kc < NC; kc++) {
        const int stg = kc & 1;
        if (kc + 1 < NC) {
            load_stage(kc + 1, stg ^ 1);
            CP_WAIT(1);
        } else {
            CP_WAIT(0);
        }
        __syncthreads();

        const uint32_t sb = smb + stg * STG;
        #pragma unroll
        for (int ks = 0; ks < 2; ks++) {
            const uint32_t kb = (uint32_t)(lc * 16 + ks * 32);

            uint32_t a_hi[2][4], a_lo[2][4];
            #pragma unroll
            for (int mf = 0; mf < 2; mf++) {
                uint32_t ao = sb + (uint32_t)((mw * 32 + mf * 16 + lr) * ASTR) + kb;
                LDSM_X4(a_hi[mf][0], a_hi[mf][1], a_hi[mf][2], a_hi[mf][3], ao + SM_AHI);
                LDSM_X4(a_lo[mf][0], a_lo[mf][1], a_lo[mf][2], a_lo[mf][3], ao + SM_ALO);
            }

            #pragma unroll
            for (int np = 0; np < 4; np++) {
                uint32_t bo = sb + (uint32_t)((nw * 64 + np * 16 + lr) * ASTR) + kb;
                uint32_t bh0, bh1, bh2, bh3, bl0, bl1, bl2, bl3;
                LDSM_X4(bh0, bh1, bh2, bh3, bo + SM_BHI);
                LDSM_X4(bl0, bl1, bl2, bl3, bo + SM_BLO);
                mma16816(acc[0][np * 2 + 0], a_hi[0], bh0, bh2);
                mma16816(acc[0][np * 2 + 1], a_hi[0], bh1, bh3);
                mma16816(acc[1][np * 2 + 0], a_hi[1], bh0, bh2);
                mma16816(acc[1][np * 2 + 1], a_hi[1], bh1, bh3);
                mma16816(acc[0][np * 2 + 0], a_hi[0], bl0, bl2);
                mma16816(acc[0][np * 2 + 1], a_hi[0], bl1, bl3);
                mma16816(acc[1][np * 2 + 0], a_hi[1], bl0, bl2);
                mma16816(acc[1][np * 2 + 1], a_hi[1], bl1, bl3);
                mma16816(acc[0][np * 2 + 0], a_lo[0], bh0, bh2);
                mma16816(acc[0][np * 2 + 1], a_lo[0], bh1, bh3);
                mma16816(acc[1][np * 2 + 0], a_lo[1], bh0, bh2);
                mma16816(acc[1][np * 2 + 1], a_lo[1], bh1, bh3);
            }
        }
        __syncthreads();
    }

    if (MODE == 1 && col0 < 2 * C_) {
        // fused q/k prepack epilogue: fp16, q pre-scaled by 0.125*log2(e)
        const bool isk = (col0 >= C_);
        const float sc = isk ? 1.0f : 0.125f * 1.44269504089f;
        __half* dst = isk ? kfp : qf;
        const int h0 = (col0 & (C_ - 1)) >> 6;
        #pragma unroll
        for (int mf = 0; mf < 2; mf++) {
            int r_ = row0 + mw * 32 + mf * 16 + (lane >> 2);
            int bi = r_ >> 11, ti = r_ & (T_ - 1);
            #pragma unroll
            for (int nf = 0; nf < 8; nf++) {
                int cl = nw * 64 + nf * 8 + (lane & 3) * 2;
                int head = h0 + (cl >> 6), d = cl & 63;
                float bb0 = sbias[cl], bb1 = sbias[cl + 1];
                size_t base = ((size_t)(bi * NH_ + head) * T_ + ti) * PQ_ + d;
                *(uint32_t*)(dst + base) =
                    pack_f16((acc[mf][nf][0] + bb0) * sc, (acc[mf][nf][1] + bb1) * sc);
                *(uint32_t*)(dst + base + 8 * PQ_) =
                    pack_f16((acc[mf][nf][2] + bb0) * sc, (acc[mf][nf][3] + bb1) * sc);
            }
        }
    } else {
        #pragma unroll
        for (int mf = 0; mf < 2; mf++) {
            int r_ = row0 + mw * 32 + mf * 16 + (lane >> 2);
            #pragma unroll
            for (int nf = 0; nf < 8; nf++) {
                int cl = nw * 64 + nf * 8 + (lane & 3) * 2;
                float b0 = sbias[cl], b1 = sbias[cl + 1];
                float2 v0 = {acc[mf][nf][0] + b0, acc[mf][nf][1] + b1};
                float2 v1 = {acc[mf][nf][2] + b0, acc[mf][nf][3] + b1};
                *(float2*)(Cout + (size_t)r_ * N + col0 + cl) = v0;
                *(float2*)(Cout + (size_t)(r_ + 8) * N + col0 + cl) = v1;
            }
        }
    }
}

// ---------------- fp16 flash attention, 3-stage cp.async pipeline -----------
#define AT_STR 144
#define SQ_F 0
#define AST_BASE 18432
#define AST_SIZE 18432
#define AST_K 0
#define AST_V 9216
#define ATTN_SMEM (AST_BASE + 3 * AST_SIZE)   // 73728

__global__ __launch_bounds__(256, 2)
void attn_mma_kernel(const __half* __restrict__ qf, const __half* __restrict__ kf,
                     const __half* __restrict__ vf,
                     __nv_bfloat16* __restrict__ yhi, __nv_bfloat16* __restrict__ ylo)
{
    extern __shared__ char sm[];
    const uint32_t smb = smem_u32(sm);
    const int tid = threadIdx.x, lane = tid & 31, wid = tid >> 5;
    const int qb = (int)(gridDim.x - 1 - blockIdx.x);
    const int h  = blockIdx.y, b = blockIdx.z;
    const int bh = b * NH_ + h;

    // Q tile (group 0)
    {
        const int row = tid >> 1, g0 = (tid & 1) * 4;
        const size_t gbase = ((size_t)bh * T_ + qb * 128 + row) * PQ_ + g0 * 8;
        const uint32_t sbase = smb + SQ_F + (uint32_t)(row * AT_STR) + g0 * 16;
        #pragma unroll
        for (int g = 0; g < 4; g++)
            CP_ASYNC16(sbase + g * 16, (const char*)(qf + gbase + g * 8));
        CP_COMMIT();
    }

    const int srow = tid >> 2;
    const int sg   = (tid & 3) * 2;

    auto load_stage = [&](int kt, int stg) {
        const uint32_t sb = smb + AST_BASE + stg * AST_SIZE;
        const uint32_t so = (uint32_t)(srow * AT_STR + sg * 16);
        const size_t gk = ((size_t)bh * T_ + kt * 64 + srow) * PQ_ + sg * 8;
        const size_t gv = ((size_t)bh * HD_ + srow) * T_ + kt * 64 + sg * 8;
        CP_ASYNC16(sb + AST_K + so,      (const char*)(kf + gk));
        CP_ASYNC16(sb + AST_K + so + 16, (const char*)(kf + gk + 8));
        CP_ASYNC16(sb + AST_V + so,      (const char*)(vf + gv));
        CP_ASYNC16(sb + AST_V + so + 16, (const char*)(vf + gv + 8));
        CP_COMMIT();
    };

    float m0 = -1e30f, m1 = -1e30f, lsum0 = 0.f, lsum1 = 0.f;
    float o[8][4];
    #pragma unroll
    for (int j = 0; j < 8; j++)
        #pragma unroll
        for (int q = 0; q < 4; q++) o[j][q] = 0.f;

    const int lr = lane & 15, lc = lane >> 4;
    const int rowg0 = qb * 128 + wid * 16 + (lane >> 2);
    const int ntiles = 2 * qb + 2;

    load_stage(0, 0);
    load_stage(1, 1);      // ntiles >= 2 always

    int stg = 0;
    for (int kt = 0; kt < ntiles; kt++) {
        if (kt + 2 < ntiles) {
            int ns = stg + 2; if (ns >= 3) ns -= 3;
            load_stage(kt + 2, ns);
            CP_WAIT(2);
        } else if (kt + 1 < ntiles) {
            CP_WAIT(1);
        } else {
            CP_WAIT(0);
        }
        __syncthreads();

        const uint32_t sb = smb + AST_BASE + stg * AST_SIZE;

        float s[8][4];
        #pragma unroll
        for (int j = 0; j < 8; j++)
            #pragma unroll
            for (int q = 0; q < 4; q++) s[j][q] = 0.f;

        #pragma unroll
        for (int ks = 0; ks < 4; ks++) {
            const uint32_t kb = (uint32_t)(lc * 16 + ks * 32);
            uint32_t aq[4];
            uint32_t ao = smb + SQ_F + (uint32_t)((wid * 16 + lr) * AT_STR) + kb;
            LDSM_X4(aq[0], aq[1], aq[2], aq[3], ao);
            #pragma unroll
            for (int np = 0; np < 4; np++) {
                uint32_t bo = sb + AST_K + (uint32_t)((np * 16 + lr) * AT_STR) + kb;
                uint32_t b0, b1, b2, b3;
                LDSM_X4(b0, b1, b2, b3, bo);
                mma16816h(s[np * 2 + 0], aq, b0, b2);
                mma16816h(s[np * 2 + 1], aq, b1, b3);
            }
        }

        if (kt >= 2 * qb) {
            const int colb = kt * 64 + 2 * (lane & 3);
            #pragma unroll
            for (int j = 0; j < 8; j++) {
                int c0 = colb + 8 * j;
                if (c0     > rowg0)     s[j][0] = -1e30f;
                if (c0 + 1 > rowg0)     s[j][1] = -1e30f;
                if (c0     > rowg0 + 8) s[j][2] = -1e30f;
                if (c0 + 1 > rowg0 + 8) s[j][3] = -1e30f;
            }
        }

        float mx0 = -1e30f, mx1 = -1e30f;
        #pragma unroll
        for (int j = 0; j < 8; j++) {
            mx0 = fmaxf(mx0, fmaxf(s[j][0], s[j][1]));
            mx1 = fmaxf(mx1, fmaxf(s[j][2], s[j][3]));
        }
        mx0 = fmaxf(mx0, __shfl_xor_sync(0xffffffffu, mx0, 1));
        mx0 = fmaxf(mx0, __shfl_xor_sync(0xffffffffu, mx0, 2));
        mx1 = fmaxf(mx1, __shfl_xor_sync(0xffffffffu, mx1, 1));
        mx1 = fmaxf(mx1, __shfl_xor_sync(0xffffffffu, mx1, 2));

        float mn0 = fmaxf(m0, mx0), mn1 = fmaxf(m1, mx1);
        float a0 = ex2f(m0 - mn0),  a1 = ex2f(m1 - mn1);
        m0 = mn0; m1 = mn1;

        float sum0 = 0.f, sum1 = 0.f;
        #pragma unroll
        for (int j = 0; j < 8; j++) {
            s[j][0] = ex2f(s[j][0] - mn0);
            s[j][1] = ex2f(s[j][1] - mn0);
            s[j][2] = ex2f(s[j][2] - mn1);
            s[j][3] = ex2f(s[j][3] - mn1);
            sum0 += s[j][0] + s[j][1];
            sum1 += s[j][2] + s[j][3];
        }
        sum0 += __shfl_xor_sync(0xffffffffu, sum0, 1);
        sum0 += __shfl_xor_sync(0xffffffffu, sum0, 2);
        sum1 += __shfl_xor_sync(0xffffffffu, sum1, 1);
        sum1 += __shfl_xor_sync(0xffffffffu, sum1, 2);
        lsum0 = lsum0 * a0 + sum0;
        lsum1 = lsum1 * a1 + sum1;

        #pragma unroll
        for (int j = 0; j < 8; j++) {
            o[j][0] *= a0; o[j][1] *= a0;
            o[j][2] *= a1; o[j][3] *= a1;
        }

        uint32_t pf[4][4];
        #pragma unroll
        for (int s2 = 0; s2 < 4; s2++) {
            pf[s2][0] = pack_f16(s[2*s2  ][0], s[2*s2  ][1]);
            pf[s2][1] = pack_f16(s[2*s2  ][2], s[2*s2  ][3]);
            pf[s2][2] = pack_f16(s[2*s2+1][0], s[2*s2+1][1]);
            pf[s2][3] = pack_f16(s[2*s2+1][2], s[2*s2+1][3]);
        }

        #pragma unroll
        for (int s2 = 0; s2 < 4; s2++) {
            const uint32_t kb = (uint32_t)(lc * 16 + s2 * 32);
            #pragma unroll
            for (int np = 0; np < 4; np++) {
                uint32_t bo = sb + AST_V + (uint32_t)((np * 16 + lr) * AT_STR) + kb;
                uint32_t b0, b1, b2, b3;
                LDSM_X4(b0, b1, b2, b3, bo);
                mma16816h(o[np * 2 + 0], pf[s2], b0, b2);
                mma16816h(o[np * 2 + 1], pf[s2], b1, b3);
            }
        }
        __syncthreads();
        if (++stg == 3) stg = 0;
    }

    float inv0 = 1.f / lsum0, inv1 = 1.f / lsum1;
    const int tok0 = b * T_ + qb * 128 + wid * 16 + (lane >> 2);
    #pragma unroll
    for (int nf = 0; nf < 8; nf++) {
        int d = h * HD_ + nf * 8 + (lane & 3) * 2;
        uint32_t hh, ll;
        pack_hilo(o[nf][0] * inv0, o[nf][1] * inv0, hh, ll);
        *(uint32_t*)(yhi + (size_t)tok0 * C_ + d) = hh;
        *(uint32_t*)(ylo + (size_t)tok0 * C_ + d) = ll;
        pack_hilo(o[nf][2] * inv1, o[nf][3] * inv1, hh, ll);
        *(uint32_t*)(yhi + (size_t)(tok0 + 8) * C_ + d) = hh;
        *(uint32_t*)(ylo + (size_t)(tok0 + 8) * C_ + d) = ll;
    }
}

// ---------------------------------------------------------------------------
extern "C" void kernel_launch(void* const* d_in, const int* in_sizes, int n_in,
                              void* d_out, int out_size)
{
    const float* x      = (const float*)d_in[0];
    const float* W_attn = (const float*)d_in[1];
    const float* b_attn = (const float*)d_in[2];
    const float* W_proj = (const float*)d_in[3];
    const float* b_proj = (const float*)d_in[4];
    float* out = (float*)d_out;

    float* qkv_ptr;
    __nv_bfloat16 *xhi, *xlo, *wthi, *wtlo, *wpthi, *wptlf, *yhi, *ylo;
    __half *qpf, *kpf, *vtf;
    cudaGetSymbolAddress((void**)&qkv_ptr, g_qkv);
    cudaGetSymbolAddress((void**)&xhi,  g_xhi);
    cudaGetSymbolAddress((void**)&xlo,  g_xlo);
    cudaGetSymbolAddress((void**)&wthi, g_wthi);
    cudaGetSymbolAddress((void**)&wtlo, g_wtlo);
    cudaGetSymbolAddress((void**)&wpthi, g_wpthi);
    cudaGetSymbolAddress((void**)&wptlf, g_wptlo);
    cudaGetSymbolAddress((void**)&yhi,  g_yhi);
    cudaGetSymbolAddress((void**)&ylo,  g_ylo);
    cudaGetSymbolAddress((void**)&qpf, g_qpf);
    cudaGetSymbolAddress((void**)&kpf, g_kpf);
    cudaGetSymbolAddress((void**)&vtf, g_vtf);

    cudaFuncSetAttribute(gemm_mma_kernel<0>,
                         cudaFuncAttributeMaxDynamicSharedMemorySize, GEMM_SMEM);
    cudaFuncSetAttribute(gemm_mma_kernel<1>,
                         cudaFuncAttributeMaxDynamicSharedMemorySize, GEMM_SMEM);
    cudaFuncSetAttribute(attn_mma_kernel,
                         cudaFuncAttributeMaxDynamicSharedMemorySize, ATTN_SMEM);

    // 1) conversions
    convert_hilo<<<(M_ * C_) / 1024, 256>>>(x, xhi, xlo, M_ * C_);
    transpose_convert<<<dim3(3 * C_ / 32, C_ / 32), 256>>>(W_attn, wthi, wtlo, C_, 3 * C_);
    transpose_convert<<<dim3(C_ / 32, C_ / 32), 256>>>(W_proj, wpthi, wptlf, C_, C_);

    // 2) qkv GEMM with fused q/k prepack epilogue (v -> fp32 qkv)
    gemm_mma_kernel<1><<<dim3(3 * C_ / 128, M_ / 128), 256, GEMM_SMEM>>>(
        xhi, xlo, wthi, wtlo, b_attn, qkv_ptr, qpf, kpf, M_, 3 * C_, C_);

    // 3) v transpose split
    v_split<<<dim3(T_ / 64, NH_, B_), 256>>>(qkv_ptr, vtf);

    // 4) fp16 flash attention (3-stage) -> yhi/ylo
    attn_mma_kernel<<<dim3(T_ / 128, NH_, B_), 256, ATTN_SMEM>>>(
        qpf, kpf, vtf, yhi, ylo);

    // 5) out = y @ W_proj + b_proj
    gemm_mma_kernel<0><<<dim3(C_ / 128, M_ / 128), 256, GEMM_SMEM>>>(
        yhi, ylo, wpthi, wptlf, b_proj, out, nullptr, nullptr, M_, C_, C_);
}

// round 12
// speedup vs baseline: 2.1936x; 1.8752x over previous
#include <cuda_runtime.h>
#include <cuda_bf16.h>
#include <cuda_fp16.h>
#include <cstdint>
#include <math.h>

#define B_  4
#define T_  2048
#define C_  1024
#define NH_ 16
#define HD_ 64
#define M_  (B_*T_)          // 8192 tokens
#define PQ_ 72               // padded row length (144B) for q/k prepack

// ---------------- scratch (static device globals; no runtime alloc) --------
__device__ __align__(256) float   g_qkv [(size_t)M_ * 3 * C_];   // v region only used
__device__ __align__(256) __half  g_xf  [(size_t)M_ * C_];
__device__ __align__(256) __half  g_wtf [(size_t)3 * C_ * C_];   // W_attn^T fp16 [3C, C]
__device__ __align__(256) __half  g_wptf[(size_t)C_ * C_];       // W_proj^T fp16 [C, C]
__device__ __align__(256) __half  g_yf  [(size_t)M_ * C_];       // attn out fp16
__device__ __align__(256) __half  g_qpf [(size_t)B_*NH_*T_*PQ_];
__device__ __align__(256) __half  g_kpf [(size_t)B_*NH_*T_*PQ_];
__device__ __align__(256) __half  g_vtf [(size_t)B_*NH_*HD_*T_];

// ---------------- helpers ---------------------------------------------------
__device__ __forceinline__ uint32_t smem_u32(const void* p) {
    uint32_t a;
    asm("{ .reg .u64 t; cvta.to.shared.u64 t, %1; cvt.u32.u64 %0, t; }" : "=r"(a) : "l"(p));
    return a;
}

#define LDSM_X4(r0, r1, r2, r3, addr) \
    asm volatile("ldmatrix.sync.aligned.m8n8.x4.shared.b16 {%0,%1,%2,%3}, [%4];" \
        : "=r"(r0), "=r"(r1), "=r"(r2), "=r"(r3) : "r"(addr))

#define CP_ASYNC16(dst, src) \
    asm volatile("cp.async.cg.shared.global [%0], [%1], 16;" :: "r"(dst), "l"(src))
#define CP_COMMIT() asm volatile("cp.async.commit_group;" ::: "memory")
#define CP_WAIT(n)  asm volatile("cp.async.wait_group %0;" :: "n"(n) : "memory")

// fp16 MMA
__device__ __forceinline__ void mma16816h(float* d, const uint32_t* a,
                                          uint32_t b0, uint32_t b1) {
    asm("mma.sync.aligned.m16n8k16.row.col.f32.f16.f16.f32 "
        "{%0,%1,%2,%3}, {%4,%5,%6,%7}, {%8,%9}, {%0,%1,%2,%3};"
        : "+f"(d[0]), "+f"(d[1]), "+f"(d[2]), "+f"(d[3])
        : "r"(a[0]), "r"(a[1]), "r"(a[2]), "r"(a[3]), "r"(b0), "r"(b1));
}

__device__ __forceinline__ uint32_t pack_f16(float a, float b) {
    uint32_t r;
    asm("cvt.rn.f16x2.f32 %0, %1, %2;" : "=r"(r) : "f"(b), "f"(a));  // lo16 = a
    return r;
}

__device__ __forceinline__ float ex2f(float x) {
    float r; asm("ex2.approx.f32 %0, %1;" : "=f"(r) : "f"(x)); return r;
}

// ---------------- conversion kernels ----------------------------------------
__global__ __launch_bounds__(256)
void convert_f16(const float* __restrict__ in, __half* __restrict__ out, int n)
{
    int i = (blockIdx.x * 256 + threadIdx.x) * 4;
    if (i >= n) return;
    float4 v = *(const float4*)(in + i);
    *(uint2*)(out + i) = make_uint2(pack_f16(v.x, v.y), pack_f16(v.z, v.w));
}

// W [K,N] fp32 -> Wt fp16 [N,K]
__global__ __launch_bounds__(256)
void transpose_convert_f16(const float* __restrict__ W, __half* __restrict__ Tf,
                           int K, int N)
{
    __shared__ float t[32][33];
    int n0 = blockIdx.x * 32, k0 = blockIdx.y * 32;
    int tx = threadIdx.x & 31, ty = threadIdx.x >> 5;
    #pragma unroll
    for (int i = 0; i < 32; i += 8)
        t[ty + i][tx] = W[(size_t)(k0 + ty + i) * N + n0 + tx];
    __syncthreads();
    #pragma unroll
    for (int i = 0; i < 32; i += 8)
        Tf[(size_t)(n0 + ty + i) * K + k0 + tx] = __float2half_rn(t[tx][ty + i]);
}

// v-only split: fp32 qkv v-region -> transposed fp16 [bh, d, T]
__global__ __launch_bounds__(256)
void v_split(const float* __restrict__ qkv, __half* __restrict__ vf)
{
    __shared__ float vt[64][65];
    const int t0 = blockIdx.x * 64, h = blockIdx.y, b = blockIdx.z;
    const int bh = b * NH_ + h;
    const int tid = threadIdx.x;
    const int tok = tid >> 2, dseg = (tid & 3) << 4;

    const float* s = qkv + (size_t)(b * T_ + t0 + tok) * (3 * C_) + 2 * C_ + h * HD_ + dseg;
    #pragma unroll
    for (int i = 0; i < 4; i++) {
        float4 v = *(const float4*)(s + i * 4);
        vt[tok][dseg + i*4 + 0] = v.x; vt[tok][dseg + i*4 + 1] = v.y;
        vt[tok][dseg + i*4 + 2] = v.z; vt[tok][dseg + i*4 + 3] = v.w;
    }
    __syncthreads();
    {
        const int d = tid >> 2, tseg = (tid & 3) << 4;
        __half* dst = vf + ((size_t)bh * HD_ + d) * T_ + t0 + tseg;
        #pragma unroll
        for (int i = 0; i < 2; i++) {
            uint32_t p0 = pack_f16(vt[tseg+i*8+0][d], vt[tseg+i*8+1][d]);
            uint32_t p1 = pack_f16(vt[tseg+i*8+2][d], vt[tseg+i*8+3][d]);
            uint32_t p2 = pack_f16(vt[tseg+i*8+4][d], vt[tseg+i*8+5][d]);
            uint32_t p3 = pack_f16(vt[tseg+i*8+6][d], vt[tseg+i*8+7][d]);
            *(uint4*)(dst + i * 8) = make_uint4(p0, p1, p2, p3);
        }
    }
}

// ---------------- single-term fp16 pipelined GEMM ---------------------------
// C[M,N] = A[M,K] @ B[N,K]^T + bias.  1 MMA per fragment per 16-K.
// MODE 0: fp32 C (proj). MODE 1: qkv — q/k cols write fused fp16 prepack.
#define ASTR 80
#define GSTG 20480                 // 2 arrays x 128 x 80
#define SM_A  0
#define SM_B  10240
#define SM_BIAS (2 * GSTG)         // 40960
#define GEMM_SMEM (2 * GSTG + 512)

template<int MODE>
__global__ __launch_bounds__(256, 2)
void gemm_mma_kernel(const __half* __restrict__ Af, const __half* __restrict__ Bf,
                     const float* __restrict__ bias, float* __restrict__ Cout,
                     __half* __restrict__ qf, __half* __restrict__ kfp,
                     int M, int N, int K)
{
    extern __shared__ __align__(16) char sm[];
    float* sbias = (float*)(sm + SM_BIAS);
    const uint32_t smb = smem_u32(sm);

    const int tid  = threadIdx.x;
    const int wid  = tid >> 5;
    const int lane = tid & 31;
    const int mw   = wid & 3;
    const int nw   = wid >> 2;
    const int row0 = blockIdx.y * 128;
    const int col0 = blockIdx.x * 128;

    if (tid < 128) sbias[tid] = bias[col0 + tid];

    float acc[2][8][4];
    #pragma unroll
    for (int i = 0; i < 2; i++)
        #pragma unroll
        for (int j = 0; j < 8; j++)
            #pragma unroll
            for (int q = 0; q < 4; q++) acc[i][j][q] = 0.f;

    const int sr0 = tid >> 2;          // 0..63
    const int ssg = tid & 3;           // 16B granule
    const int lr = lane & 15;
    const int lc = lane >> 4;
    const int NC = K >> 5;

    auto load_stage = [&](int kc, int stg) {
        const uint32_t sb = smb + stg * GSTG;
        #pragma unroll
        for (int it = 0; it < 2; it++) {
            int r = sr0 + it * 64;
            uint32_t so = (uint32_t)(r * ASTR + ssg * 16);
            size_t ga = (size_t)(row0 + r) * K + (kc << 5) + ssg * 8;
            size_t gb = (size_t)(col0 + r) * K + (kc << 5) + ssg * 8;
            CP_ASYNC16(sb + SM_A + so, (const char*)(Af + ga));
            CP_ASYNC16(sb + SM_B + so, (const char*)(Bf + gb));
        }
        CP_COMMIT();
    };

    load_stage(0, 0);

    for (int kc = 0; kc < NC; kc++) {
        const int stg = kc & 1;
        if (kc + 1 < NC) {
            load_stage(kc + 1, stg ^ 1);
            CP_WAIT(1);
        } else {
            CP_WAIT(0);
        }
        __syncthreads();

        const uint32_t sb = smb + stg * GSTG;
        #pragma unroll
        for (int ks = 0; ks < 2; ks++) {
            const uint32_t kb = (uint32_t)(lc * 16 + ks * 32);

            uint32_t af[2][4];
            #pragma unroll
            for (int mf = 0; mf < 2; mf++) {
                uint32_t ao = sb + SM_A + (uint32_t)((mw * 32 + mf * 16 + lr) * ASTR) + kb;
                LDSM_X4(af[mf][0], af[mf][1], af[mf][2], af[mf][3], ao);
            }

            #pragma unroll
            for (int np = 0; np < 4; np++) {
                uint32_t bo = sb + SM_B + (uint32_t)((nw * 64 + np * 16 + lr) * ASTR) + kb;
                uint32_t b0, b1, b2, b3;
                LDSM_X4(b0, b1, b2, b3, bo);
                mma16816h(acc[0][np * 2 + 0], af[0], b0, b2);
                mma16816h(acc[0][np * 2 + 1], af[0], b1, b3);
                mma16816h(acc[1][np * 2 + 0], af[1], b0, b2);
                mma16816h(acc[1][np * 2 + 1], af[1], b1, b3);
            }
        }
        __syncthreads();
    }

    if (MODE == 1 && col0 < 2 * C_) {
        // fused q/k prepack epilogue: fp16, q pre-scaled by 0.125*log2(e)
        const bool isk = (col0 >= C_);
        const float sc = isk ? 1.0f : 0.125f * 1.44269504089f;
        __half* dst = isk ? kfp : qf;
        const int h0 = (col0 & (C_ - 1)) >> 6;
        #pragma unroll
        for (int mf = 0; mf < 2; mf++) {
            int r_ = row0 + mw * 32 + mf * 16 + (lane >> 2);
            int bi = r_ >> 11, ti = r_ & (T_ - 1);
            #pragma unroll
            for (int nf = 0; nf < 8; nf++) {
                int cl = nw * 64 + nf * 8 + (lane & 3) * 2;
                int head = h0 + (cl >> 6), d = cl & 63;
                float bb0 = sbias[cl], bb1 = sbias[cl + 1];
                size_t base = ((size_t)(bi * NH_ + head) * T_ + ti) * PQ_ + d;
                *(uint32_t*)(dst + base) =
                    pack_f16((acc[mf][nf][0] + bb0) * sc, (acc[mf][nf][1] + bb1) * sc);
                *(uint32_t*)(dst + base + 8 * PQ_) =
                    pack_f16((acc[mf][nf][2] + bb0) * sc, (acc[mf][nf][3] + bb1) * sc);
            }
        }
    } else {
        #pragma unroll
        for (int mf = 0; mf < 2; mf++) {
            int r_ = row0 + mw * 32 + mf * 16 + (lane >> 2);
            #pragma unroll
            for (int nf = 0; nf < 8; nf++) {
                int cl = nw * 64 + nf * 8 + (lane & 3) * 2;
                float b0 = sbias[cl], b1 = sbias[cl + 1];
                float2 v0 = {acc[mf][nf][0] + b0, acc[mf][nf][1] + b1};
                float2 v1 = {acc[mf][nf][2] + b0, acc[mf][nf][3] + b1};
                *(float2*)(Cout + (size_t)r_ * N + col0 + cl) = v0;
                *(float2*)(Cout + (size_t)(r_ + 8) * N + col0 + cl) = v1;
            }
        }
    }
}

// ---------------- fp16 flash attention, 3-stage cp.async pipeline -----------
#define AT_STR 144
#define SQ_F 0
#define AST_BASE 18432
#define AST_SIZE 18432
#define AST_K 0
#define AST_V 9216
#define ATTN_SMEM (AST_BASE + 3 * AST_SIZE)   // 73728

__global__ __launch_bounds__(256, 2)
void attn_mma_kernel(const __half* __restrict__ qf, const __half* __restrict__ kf,
                     const __half* __restrict__ vf, __half* __restrict__ yf)
{
    extern __shared__ char sm[];
    const uint32_t smb = smem_u32(sm);
    const int tid = threadIdx.x, lane = tid & 31, wid = tid >> 5;
    const int qb = (int)(gridDim.x - 1 - blockIdx.x);
    const int h  = blockIdx.y, b = blockIdx.z;
    const int bh = b * NH_ + h;

    // Q tile (group 0)
    {
        const int row = tid >> 1, g0 = (tid & 1) * 4;
        const size_t gbase = ((size_t)bh * T_ + qb * 128 + row) * PQ_ + g0 * 8;
        const uint32_t sbase = smb + SQ_F + (uint32_t)(row * AT_STR) + g0 * 16;
        #pragma unroll
        for (int g = 0; g < 4; g++)
            CP_ASYNC16(sbase + g * 16, (const char*)(qf + gbase + g * 8));
        CP_COMMIT();
    }

    const int srow = tid >> 2;
    const int sg   = (tid & 3) * 2;

    auto load_stage = [&](int kt, int stg) {
        const uint32_t sb = smb + AST_BASE + stg * AST_SIZE;
        const uint32_t so = (uint32_t)(srow * AT_STR + sg * 16);
        const size_t gk = ((size_t)bh * T_ + kt * 64 + srow) * PQ_ + sg * 8;
        const size_t gv = ((size_t)bh * HD_ + srow) * T_ + kt * 64 + sg * 8;
        CP_ASYNC16(sb + AST_K + so,      (const char*)(kf + gk));
        CP_ASYNC16(sb + AST_K + so + 16, (const char*)(kf + gk + 8));
        CP_ASYNC16(sb + AST_V + so,      (const char*)(vf + gv));
        CP_ASYNC16(sb + AST_V + so + 16, (const char*)(vf + gv + 8));
        CP_COMMIT();
    };

    float m0 = -1e30f, m1 = -1e30f, lsum0 = 0.f, lsum1 = 0.f;
    float o[8][4];
    #pragma unroll
    for (int j = 0; j < 8; j++)
        #pragma unroll
        for (int q = 0; q < 4; q++) o[j][q] = 0.f;

    const int lr = lane & 15, lc = lane >> 4;
    const int rowg0 = qb * 128 + wid * 16 + (lane >> 2);
    const int ntiles = 2 * qb + 2;

    load_stage(0, 0);
    load_stage(1, 1);      // ntiles >= 2 always

    int stg = 0;
    for (int kt = 0; kt < ntiles; kt++) {
        if (kt + 2 < ntiles) {
            int ns = stg + 2; if (ns >= 3) ns -= 3;
            load_stage(kt + 2, ns);
            CP_WAIT(2);
        } else if (kt + 1 < ntiles) {
            CP_WAIT(1);
        } else {
            CP_WAIT(0);
        }
        __syncthreads();

        const uint32_t sb = smb + AST_BASE + stg * AST_SIZE;

        float s[8][4];
        #pragma unroll
        for (int j = 0; j < 8; j++)
            #pragma unroll
            for (int q = 0; q < 4; q++) s[j][q] = 0.f;

        #pragma unroll
        for (int ks = 0; ks < 4; ks++) {
            const uint32_t kb = (uint32_t)(lc * 16 + ks * 32);
            uint32_t aq[4];
            uint32_t ao = smb + SQ_F + (uint32_t)((wid * 16 + lr) * AT_STR) + kb;
            LDSM_X4(aq[0], aq[1], aq[2], aq[3], ao);
            #pragma unroll
            for (int np = 0; np < 4; np++) {
                uint32_t bo = sb + AST_K + (uint32_t)((np * 16 + lr) * AT_STR) + kb;
                uint32_t b0, b1, b2, b3;
                LDSM_X4(b0, b1, b2, b3, bo);
                mma16816h(s[np * 2 + 0], aq, b0, b2);
                mma16816h(s[np * 2 + 1], aq, b1, b3);
            }
        }

        if (kt >= 2 * qb) {
            const int colb = kt * 64 + 2 * (lane & 3);
            #pragma unroll
            for (int j = 0; j < 8; j++) {
                int c0 = colb + 8 * j;
                if (c0     > rowg0)     s[j][0] = -1e30f;
                if (c0 + 1 > rowg0)     s[j][1] = -1e30f;
                if (c0     > rowg0 + 8) s[j][2] = -1e30f;
                if (c0 + 1 > rowg0 + 8) s[j][3] = -1e30f;
            }
        }

        float mx0 = -1e30f, mx1 = -1e30f;
        #pragma unroll
        for (int j = 0; j < 8; j++) {
            mx0 = fmaxf(mx0, fmaxf(s[j][0], s[j][1]));
            mx1 = fmaxf(mx1, fmaxf(s[j][2], s[j][3]));
        }
        mx0 = fmaxf(mx0, __shfl_xor_sync(0xffffffffu, mx0, 1));
        mx0 = fmaxf(mx0, __shfl_xor_sync(0xffffffffu, mx0, 2));
        mx1 = fmaxf(mx1, __shfl_xor_sync(0xffffffffu, mx1, 1));
        mx1 = fmaxf(mx1, __shfl_xor_sync(0xffffffffu, mx1, 2));

        float mn0 = fmaxf(m0, mx0), mn1 = fmaxf(m1, mx1);
        float a0 = ex2f(m0 - mn0),  a1 = ex2f(m1 - mn1);
        m0 = mn0; m1 = mn1;

        float sum0 = 0.f, sum1 = 0.f;
        #pragma unroll
        for (int j = 0; j < 8; j++) {
            s[j][0] = ex2f(s[j][0] - mn0);
            s[j][1] = ex2f(s[j][1] - mn0);
            s[j][2] = ex2f(s[j][2] - mn1);
            s[j][3] = ex2f(s[j][3] - mn1);
            sum0 += s[j][0] + s[j][1];
            sum1 += s[j][2] + s[j][3];
        }
        sum0 += __shfl_xor_sync(0xffffffffu, sum0, 1);
        sum0 += __shfl_xor_sync(0xffffffffu, sum0, 2);
        sum1 += __shfl_xor_sync(0xffffffffu, sum1, 1);
        sum1 += __shfl_xor_sync(0xffffffffu, sum1, 2);
        lsum0 = lsum0 * a0 + sum0;
        lsum1 = lsum1 * a1 + sum1;

        #pragma unroll
        for (int j = 0; j < 8; j++) {
            o[j][0] *= a0; o[j][1] *= a0;
            o[j][2] *= a1; o[j][3] *= a1;
        }

        uint32_t pf[4][4];
        #pragma unroll
        for (int s2 = 0; s2 < 4; s2++) {
            pf[s2][0] = pack_f16(s[2*s2  ][0], s[2*s2  ][1]);
            pf[s2][1] = pack_f16(s[2*s2  ][2], s[2*s2  ][3]);
            pf[s2][2] = pack_f16(s[2*s2+1][0], s[2*s2+1][1]);
            pf[s2][3] = pack_f16(s[2*s2+1][2], s[2*s2+1][3]);
        }

        #pragma unroll
        for (int s2 = 0; s2 < 4; s2++) {
            const uint32_t kb = (uint32_t)(lc * 16 + s2 * 32);
            #pragma unroll
            for (int np = 0; np < 4; np++) {
                uint32_t bo = sb + AST_V + (uint32_t)((np * 16 + lr) * AT_STR) + kb;
                uint32_t b0, b1, b2, b3;
                LDSM_X4(b0, b1, b2, b3, bo);
                mma16816h(o[np * 2 + 0], pf[s2], b0, b2);
                mma16816h(o[np * 2 + 1], pf[s2], b1, b3);
            }
        }
        __syncthreads();
        if (++stg == 3) stg = 0;
    }

    float inv0 = 1.f / lsum0, inv1 = 1.f / lsum1;
    const int tok0 = b * T_ + qb * 128 + wid * 16 + (lane >> 2);
    #pragma unroll
    for (int nf = 0; nf < 8; nf++) {
        int d = h * HD_ + nf * 8 + (lane & 3) * 2;
        *(uint32_t*)(yf + (size_t)tok0 * C_ + d)       = pack_f16(o[nf][0] * inv0, o[nf][1] * inv0);
        *(uint32_t*)(yf + (size_t)(tok0 + 8) * C_ + d) = pack_f16(o[nf][2] * inv1, o[nf][3] * inv1);
    }
}

// ---------------------------------------------------------------------------
extern "C" void kernel_launch(void* const* d_in, const int* in_sizes, int n_in,
                              void* d_out, int out_size)
{
    const float* x      = (const float*)d_in[0];
    const float* W_attn = (const float*)d_in[1];
    const float* b_attn = (const float*)d_in[2];
    const float* W_proj = (const float*)d_in[3];
    const float* b_proj = (const float*)d_in[4];
    float* out = (float*)d_out;

    float* qkv_ptr;
    __half *xf, *wtf, *wptf, *yf, *qpf, *kpf, *vtf;
    cudaGetSymbolAddress((void**)&qkv_ptr, g_qkv);
    cudaGetSymbolAddress((void**)&xf,   g_xf);
    cudaGetSymbolAddress((void**)&wtf,  g_wtf);
    cudaGetSymbolAddress((void**)&wptf, g_wptf);
    cudaGetSymbolAddress((void**)&yf,   g_yf);
    cudaGetSymbolAddress((void**)&qpf,  g_qpf);
    cudaGetSymbolAddress((void**)&kpf,  g_kpf);
    cudaGetSymbolAddress((void**)&vtf,  g_vtf);

    cudaFuncSetAttribute(gemm_mma_kernel<0>,
                         cudaFuncAttributeMaxDynamicSharedMemorySize, GEMM_SMEM);
    cudaFuncSetAttribute(gemm_mma_kernel<1>,
                         cudaFuncAttributeMaxDynamicSharedMemorySize, GEMM_SMEM);
    cudaFuncSetAttribute(attn_mma_kernel,
                         cudaFuncAttributeMaxDynamicSharedMemorySize, ATTN_SMEM);

    // 1) conversions (single fp16)
    convert_f16<<<(M_ * C_) / 1024, 256>>>(x, xf, M_ * C_);
    transpose_convert_f16<<<dim3(3 * C_ / 32, C_ / 32), 256>>>(W_attn, wtf, C_, 3 * C_);
    transpose_convert_f16<<<dim3(C_ / 32, C_ / 32), 256>>>(W_proj, wptf, C_, C_);

    // 2) qkv GEMM (1 MMA/fragment) with fused q/k prepack epilogue
    gemm_mma_kernel<1><<<dim3(3 * C_ / 128, M_ / 128), 256, GEMM_SMEM>>>(
        xf, wtf, b_attn, qkv_ptr, qpf, kpf, M_, 3 * C_, C_);

    // 3) v transpose split
    v_split<<<dim3(T_ / 64, NH_, B_), 256>>>(qkv_ptr, vtf);

    // 4) fp16 flash attention (3-stage) -> yf
    attn_mma_kernel<<<dim3(T_ / 128, NH_, B_), 256, ATTN_SMEM>>>(qpf, kpf, vtf, yf);

    // 5) out = y @ W_proj + b_proj (1 MMA/fragment)
    gemm_mma_kernel<0><<<dim3(C_ / 128, M_ / 128), 256, GEMM_SMEM>>>(
        yf, wptf, b_proj, out, nullptr, nullptr, M_, C_, C_);
}

// round 13
// speedup vs baseline: 2.2447x; 1.0233x over previous
#include <cuda_runtime.h>
#include <cuda_bf16.h>
#include <cuda_fp16.h>
#include <cstdint>
#include <math.h>

#define B_  4
#define T_  2048
#define C_  1024
#define NH_ 16
#define HD_ 64
#define M_  (B_*T_)          // 8192 tokens
#define PQ_ 72               // padded row length (144B) for q/k prepack

// ---------------- scratch (static device globals; no runtime alloc) --------
__device__ __align__(256) __half  g_xf  [(size_t)M_ * C_];
__device__ __align__(256) __half  g_wtf [(size_t)3 * C_ * C_];   // W_attn^T fp16 [3C, C]
__device__ __align__(256) __half  g_wptf[(size_t)C_ * C_];       // W_proj^T fp16 [C, C]
__device__ __align__(256) __half  g_yf  [(size_t)M_ * C_];       // attn out fp16
__device__ __align__(256) __half  g_qpf [(size_t)B_*NH_*T_*PQ_];
__device__ __align__(256) __half  g_kpf [(size_t)B_*NH_*T_*PQ_];
__device__ __align__(256) __half  g_vtf [(size_t)B_*NH_*HD_*T_];

// ---------------- helpers ---------------------------------------------------
__device__ __forceinline__ uint32_t smem_u32(const void* p) {
    uint32_t a;
    asm("{ .reg .u64 t; cvta.to.shared.u64 t, %1; cvt.u32.u64 %0, t; }" : "=r"(a) : "l"(p));
    return a;
}

#define LDSM_X4(r0, r1, r2, r3, addr) \
    asm volatile("ldmatrix.sync.aligned.m8n8.x4.shared.b16 {%0,%1,%2,%3}, [%4];" \
        : "=r"(r0), "=r"(r1), "=r"(r2), "=r"(r3) : "r"(addr))

#define CP_ASYNC16(dst, src) \
    asm volatile("cp.async.cg.shared.global [%0], [%1], 16;" :: "r"(dst), "l"(src))
#define CP_COMMIT() asm volatile("cp.async.commit_group;" ::: "memory")
#define CP_WAIT(n)  asm volatile("cp.async.wait_group %0;" :: "n"(n) : "memory")

// fp16 MMA
__device__ __forceinline__ void mma16816h(float* d, const uint32_t* a,
                                          uint32_t b0, uint32_t b1) {
    asm("mma.sync.aligned.m16n8k16.row.col.f32.f16.f16.f32 "
        "{%0,%1,%2,%3}, {%4,%5,%6,%7}, {%8,%9}, {%0,%1,%2,%3};"
        : "+f"(d[0]), "+f"(d[1]), "+f"(d[2]), "+f"(d[3])
        : "r"(a[0]), "r"(a[1]), "r"(a[2]), "r"(a[3]), "r"(b0), "r"(b1));
}

__device__ __forceinline__ uint32_t pack_f16(float a, float b) {
    uint32_t r;
    asm("cvt.rn.f16x2.f32 %0, %1, %2;" : "=r"(r) : "f"(b), "f"(a));  // lo16 = a
    return r;
}

__device__ __forceinline__ float ex2f(float x) {
    float r; asm("ex2.approx.f32 %0, %1;" : "=f"(r) : "f"(x)); return r;
}

// ---------------- conversion kernels ----------------------------------------
__global__ __launch_bounds__(256)
void convert_f16(const float* __restrict__ in, __half* __restrict__ out, int n)
{
    int i = (blockIdx.x * 256 + threadIdx.x) * 4;
    if (i >= n) return;
    float4 v = *(const float4*)(in + i);
    *(uint2*)(out + i) = make_uint2(pack_f16(v.x, v.y), pack_f16(v.z, v.w));
}

// W [K,N] fp32 -> Wt fp16 [N,K]
__global__ __launch_bounds__(256)
void transpose_convert_f16(const float* __restrict__ W, __half* __restrict__ Tf,
                           int K, int N)
{
    __shared__ float t[32][33];
    int n0 = blockIdx.x * 32, k0 = blockIdx.y * 32;
    int tx = threadIdx.x & 31, ty = threadIdx.x >> 5;
    #pragma unroll
    for (int i = 0; i < 32; i += 8)
        t[ty + i][tx] = W[(size_t)(k0 + ty + i) * N + n0 + tx];
    __syncthreads();
    #pragma unroll
    for (int i = 0; i < 32; i += 8)
        Tf[(size_t)(n0 + ty + i) * K + k0 + tx] = __float2half_rn(t[tx][ty + i]);
}

// ---------------- single-term fp16 pipelined GEMM ---------------------------
// C[M,N] = A[M,K] @ B[N,K]^T + bias.  1 MMA per fragment per 16-K.
// MODE 0: fp32 C (proj).
// MODE 1: qkv — q/k cols write fused fp16 prepack; v cols write transposed
//         fp16 [bh, d, T] directly (no intermediate qkv buffer).
#define ASTR 80
#define GSTG 20480                 // 2 arrays x 128 x 80
#define SM_A  0
#define SM_B  10240
#define SM_BIAS (2 * GSTG)         // 40960
#define GEMM_SMEM (2 * GSTG + 512)

template<int MODE>
__global__ __launch_bounds__(256, 2)
void gemm_mma_kernel(const __half* __restrict__ Af, const __half* __restrict__ Bf,
                     const float* __restrict__ bias, float* __restrict__ Cout,
                     __half* __restrict__ qf, __half* __restrict__ kfp,
                     __half* __restrict__ vf,
                     int M, int N, int K)
{
    extern __shared__ __align__(16) char sm[];
    float* sbias = (float*)(sm + SM_BIAS);
    const uint32_t smb = smem_u32(sm);

    const int tid  = threadIdx.x;
    const int wid  = tid >> 5;
    const int lane = tid & 31;
    const int mw   = wid & 3;
    const int nw   = wid >> 2;
    const int row0 = blockIdx.y * 128;
    const int col0 = blockIdx.x * 128;

    if (tid < 128) sbias[tid] = bias[col0 + tid];

    float acc[2][8][4];
    #pragma unroll
    for (int i = 0; i < 2; i++)
        #pragma unroll
        for (int j = 0; j < 8; j++)
            #pragma unroll
            for (int q = 0; q < 4; q++) acc[i][j][q] = 0.f;

    const int sr0 = tid >> 2;          // 0..63
    const int ssg = tid & 3;           // 16B granule
    const int lr = lane & 15;
    const int lc = lane >> 4;
    const int NC = K >> 5;

    auto load_stage = [&](int kc, int stg) {
        const uint32_t sb = smb + stg * GSTG;
        #pragma unroll
        for (int it = 0; it < 2; it++) {
            int r = sr0 + it * 64;
            uint32_t so = (uint32_t)(r * ASTR + ssg * 16);
            size_t ga = (size_t)(row0 + r) * K + (kc << 5) + ssg * 8;
            size_t gb = (size_t)(col0 + r) * K + (kc << 5) + ssg * 8;
            CP_ASYNC16(sb + SM_A + so, (const char*)(Af + ga));
            CP_ASYNC16(sb + SM_B + so, (const char*)(Bf + gb));
        }
        CP_COMMIT();
    };

    load_stage(0, 0);

    for (int kc = 0; kc < NC; kc++) {
        const int stg = kc & 1;
        if (kc + 1 < NC) {
            load_stage(kc + 1, stg ^ 1);
            CP_WAIT(1);
        } else {
            CP_WAIT(0);
        }
        __syncthreads();

        const uint32_t sb = smb + stg * GSTG;
        #pragma unroll
        for (int ks = 0; ks < 2; ks++) {
            const uint32_t kb = (uint32_t)(lc * 16 + ks * 32);

            uint32_t af[2][4];
            #pragma unroll
            for (int mf = 0; mf < 2; mf++) {
                uint32_t ao = sb + SM_A + (uint32_t)((mw * 32 + mf * 16 + lr) * ASTR) + kb;
                LDSM_X4(af[mf][0], af[mf][1], af[mf][2], af[mf][3], ao);
            }

            #pragma unroll
            for (int np = 0; np < 4; np++) {
                uint32_t bo = sb + SM_B + (uint32_t)((nw * 64 + np * 16 + lr) * ASTR) + kb;
                uint32_t b0, b1, b2, b3;
                LDSM_X4(b0, b1, b2, b3, bo);
                mma16816h(acc[0][np * 2 + 0], af[0], b0, b2);
                mma16816h(acc[0][np * 2 + 1], af[0], b1, b3);
                mma16816h(acc[1][np * 2 + 0], af[1], b0, b2);
                mma16816h(acc[1][np * 2 + 1], af[1], b1, b3);
            }
        }
        __syncthreads();
    }

    if (MODE == 1) {
        if (col0 < 2 * C_) {
            // fused q/k prepack epilogue: fp16, q pre-scaled by 0.125*log2(e)
            const bool isk = (col0 >= C_);
            const float sc = isk ? 1.0f : 0.125f * 1.44269504089f;
            __half* dst = isk ? kfp : qf;
            const int h0 = (col0 & (C_ - 1)) >> 6;
            #pragma unroll
            for (int mf = 0; mf < 2; mf++) {
                int r_ = row0 + mw * 32 + mf * 16 + (lane >> 2);
                int bi = r_ >> 11, ti = r_ & (T_ - 1);
                #pragma unroll
                for (int nf = 0; nf < 8; nf++) {
                    int cl = nw * 64 + nf * 8 + (lane & 3) * 2;
                    int head = h0 + (cl >> 6), d = cl & 63;
                    float bb0 = sbias[cl], bb1 = sbias[cl + 1];
                    size_t base = ((size_t)(bi * NH_ + head) * T_ + ti) * PQ_ + d;
                    *(uint32_t*)(dst + base) =
                        pack_f16((acc[mf][nf][0] + bb0) * sc, (acc[mf][nf][1] + bb1) * sc);
                    *(uint32_t*)(dst + base + 8 * PQ_) =
                        pack_f16((acc[mf][nf][2] + bb0) * sc, (acc[mf][nf][3] + bb1) * sc);
                }
            }
        } else {
            // fused v epilogue: write transposed fp16 [bh, d, T]
            const int h0 = (col0 - 2 * C_) >> 6;
            #pragma unroll
            for (int mf = 0; mf < 2; mf++) {
                int r_ = row0 + mw * 32 + mf * 16 + (lane >> 2);
                int bi = r_ >> 11, ti = r_ & (T_ - 1);
                #pragma unroll
                for (int nf = 0; nf < 8; nf++) {
                    int cl = nw * 64 + nf * 8 + (lane & 3) * 2;
                    int head = h0 + (cl >> 6), d = cl & 63;
                    float bb0 = sbias[cl], bb1 = sbias[cl + 1];
                    size_t base = ((size_t)(bi * NH_ + head) * HD_ + d) * T_ + ti;
                    vf[base]          = __float2half_rn(acc[mf][nf][0] + bb0);
                    vf[base + T_]     = __float2half_rn(acc[mf][nf][1] + bb1);
                    vf[base + 8]      = __float2half_rn(acc[mf][nf][2] + bb0);
                    vf[base + T_ + 8] = __float2half_rn(acc[mf][nf][3] + bb1);
                }
            }
        }
    } else {
        #pragma unroll
        for (int mf = 0; mf < 2; mf++) {
            int r_ = row0 + mw * 32 + mf * 16 + (lane >> 2);
            #pragma unroll
            for (int nf = 0; nf < 8; nf++) {
                int cl = nw * 64 + nf * 8 + (lane & 3) * 2;
                float b0 = sbias[cl], b1 = sbias[cl + 1];
                float2 v0 = {acc[mf][nf][0] + b0, acc[mf][nf][1] + b1};
                float2 v1 = {acc[mf][nf][2] + b0, acc[mf][nf][3] + b1};
                *(float2*)(Cout + (size_t)r_ * N + col0 + cl) = v0;
                *(float2*)(Cout + (size_t)(r_ + 8) * N + col0 + cl) = v1;
            }
        }
    }
}

// ---------------- fp16 flash attention, 3-stage cp.async pipeline -----------
#define AT_STR 144
#define SQ_F 0
#define AST_BASE 18432
#define AST_SIZE 18432
#define AST_K 0
#define AST_V 9216
#define ATTN_SMEM (AST_BASE + 3 * AST_SIZE)   // 73728

__global__ __launch_bounds__(256, 2)
void attn_mma_kernel(const __half* __restrict__ qf, const __half* __restrict__ kf,
                     const __half* __restrict__ vf, __half* __restrict__ yf)
{
    extern __shared__ char sm[];
    const uint32_t smb = smem_u32(sm);
    const int tid = threadIdx.x, lane = tid & 31, wid = tid >> 5;
    const int qb = (int)(gridDim.x - 1 - blockIdx.x);
    const int h  = blockIdx.y, b = blockIdx.z;
    const int bh = b * NH_ + h;

    // Q tile (group 0)
    {
        const int row = tid >> 1, g0 = (tid & 1) * 4;
        const size_t gbase = ((size_t)bh * T_ + qb * 128 + row) * PQ_ + g0 * 8;
        const uint32_t sbase = smb + SQ_F + (uint32_t)(row * AT_STR) + g0 * 16;
        #pragma unroll
        for (int g = 0; g < 4; g++)
            CP_ASYNC16(sbase + g * 16, (const char*)(qf + gbase + g * 8));
        CP_COMMIT();
    }

    const int srow = tid >> 2;
    const int sg   = (tid & 3) * 2;

    auto load_stage = [&](int kt, int stg) {
        const uint32_t sb = smb + AST_BASE + stg * AST_SIZE;
        const uint32_t so = (uint32_t)(srow * AT_STR + sg * 16);
        const size_t gk = ((size_t)bh * T_ + kt * 64 + srow) * PQ_ + sg * 8;
        const size_t gv = ((size_t)bh * HD_ + srow) * T_ + kt * 64 + sg * 8;
        CP_ASYNC16(sb + AST_K + so,      (const char*)(kf + gk));
        CP_ASYNC16(sb + AST_K + so + 16, (const char*)(kf + gk + 8));
        CP_ASYNC16(sb + AST_V + so,      (const char*)(vf + gv));
        CP_ASYNC16(sb + AST_V + so + 16, (const char*)(vf + gv + 8));
        CP_COMMIT();
    };

    float m0 = -1e30f, m1 = -1e30f, lsum0 = 0.f, lsum1 = 0.f;
    float o[8][4];
    #pragma unroll
    for (int j = 0; j < 8; j++)
        #pragma unroll
        for (int q = 0; q < 4; q++) o[j][q] = 0.f;

    const int lr = lane & 15, lc = lane >> 4;
    const int rowg0 = qb * 128 + wid * 16 + (lane >> 2);
    const int ntiles = 2 * qb + 2;

    load_stage(0, 0);
    load_stage(1, 1);      // ntiles >= 2 always

    int stg = 0;
    for (int kt = 0; kt < ntiles; kt++) {
        if (kt + 2 < ntiles) {
            int ns = stg + 2; if (ns >= 3) ns -= 3;
            load_stage(kt + 2, ns);
            CP_WAIT(2);
        } else if (kt + 1 < ntiles) {
            CP_WAIT(1);
        } else {
            CP_WAIT(0);
        }
        __syncthreads();

        const uint32_t sb = smb + AST_BASE + stg * AST_SIZE;

        float s[8][4];
        #pragma unroll
        for (int j = 0; j < 8; j++)
            #pragma unroll
            for (int q = 0; q < 4; q++) s[j][q] = 0.f;

        #pragma unroll
        for (int ks = 0; ks < 4; ks++) {
            const uint32_t kb = (uint32_t)(lc * 16 + ks * 32);
            uint32_t aq[4];
            uint32_t ao = smb + SQ_F + (uint32_t)((wid * 16 + lr) * AT_STR) + kb;
            LDSM_X4(aq[0], aq[1], aq[2], aq[3], ao);
            #pragma unroll
            for (int np = 0; np < 4; np++) {
                uint32_t bo = sb + AST_K + (uint32_t)((np * 16 + lr) * AT_STR) + kb;
                uint32_t b0, b1, b2, b3;
                LDSM_X4(b0, b1, b2, b3, bo);
                mma16816h(s[np * 2 + 0], aq, b0, b2);
                mma16816h(s[np * 2 + 1], aq, b1, b3);
            }
        }

        if (kt >= 2 * qb) {
            const int colb = kt * 64 + 2 * (lane & 3);
            #pragma unroll
            for (int j = 0; j < 8; j++) {
                int c0 = colb + 8 * j;
                if (c0     > rowg0)     s[j][0] = -1e30f;
                if (c0 + 1 > rowg0)     s[j][1] = -1e30f;
                if (c0     > rowg0 + 8) s[j][2] = -1e30f;
                if (c0 + 1 > rowg0 + 8) s[j][3] = -1e30f;
            }
        }

        float mx0 = -1e30f, mx1 = -1e30f;
        #pragma unroll
        for (int j = 0; j < 8; j++) {
            mx0 = fmaxf(mx0, fmaxf(s[j][0], s[j][1]));
            mx1 = fmaxf(mx1, fmaxf(s[j][2], s[j][3]));
        }
        mx0 = fmaxf(mx0, __shfl_xor_sync(0xffffffffu, mx0, 1));
        mx0 = fmaxf(mx0, __shfl_xor_sync(0xffffffffu, mx0, 2));
        mx1 = fmaxf(mx1, __shfl_xor_sync(0xffffffffu, mx1, 1));
        mx1 = fmaxf(mx1, __shfl_xor_sync(0xffffffffu, mx1, 2));

        float mn0 = fmaxf(m0, mx0), mn1 = fmaxf(m1, mx1);
        float a0 = ex2f(m0 - mn0),  a1 = ex2f(m1 - mn1);
        m0 = mn0; m1 = mn1;

        float sum0 = 0.f, sum1 = 0.f;
        #pragma unroll
        for (int j = 0; j < 8; j++) {
            s[j][0] = ex2f(s[j][0] - mn0);
            s[j][1] = ex2f(s[j][1] - mn0);
            s[j][2] = ex2f(s[j][2] - mn1);
            s[j][3] = ex2f(s[j][3] - mn1);
            sum0 += s[j][0] + s[j][1];
            sum1 += s[j][2] + s[j][3];
        }
        sum0 += __shfl_xor_sync(0xffffffffu, sum0, 1);
        sum0 += __shfl_xor_sync(0xffffffffu, sum0, 2);
        sum1 += __shfl_xor_sync(0xffffffffu, sum1, 1);
        sum1 += __shfl_xor_sync(0xffffffffu, sum1, 2);
        lsum0 = lsum0 * a0 + sum0;
        lsum1 = lsum1 * a1 + sum1;

        #pragma unroll
        for (int j = 0; j < 8; j++) {
            o[j][0] *= a0; o[j][1] *= a0;
            o[j][2] *= a1; o[j][3] *= a1;
        }

        uint32_t pf[4][4];
        #pragma unroll
        for (int s2 = 0; s2 < 4; s2++) {
            pf[s2][0] = pack_f16(s[2*s2  ][0], s[2*s2  ][1]);
            pf[s2][1] = pack_f16(s[2*s2  ][2], s[2*s2  ][3]);
            pf[s2][2] = pack_f16(s[2*s2+1][0], s[2*s2+1][1]);
            pf[s2][3] = pack_f16(s[2*s2+1][2], s[2*s2+1][3]);
        }

        #pragma unroll
        for (int s2 = 0; s2 < 4; s2++) {
            const uint32_t kb = (uint32_t)(lc * 16 + s2 * 32);
            #pragma unroll
            for (int np = 0; np < 4; np++) {
                uint32_t bo = sb + AST_V + (uint32_t)((np * 16 + lr) * AT_STR) + kb;
                uint32_t b0, b1, b2, b3;
                LDSM_X4(b0, b1, b2, b3, bo);
                mma16816h(o[np * 2 + 0], pf[s2], b0, b2);
                mma16816h(o[np * 2 + 1], pf[s2], b1, b3);
            }
        }
        __syncthreads();
        if (++stg == 3) stg = 0;
    }

    float inv0 = 1.f / lsum0, inv1 = 1.f / lsum1;
    const int tok0 = b * T_ + qb * 128 + wid * 16 + (lane >> 2);
    #pragma unroll
    for (int nf = 0; nf < 8; nf++) {
        int d = h * HD_ + nf * 8 + (lane & 3) * 2;
        *(uint32_t*)(yf + (size_t)tok0 * C_ + d)       = pack_f16(o[nf][0] * inv0, o[nf][1] * inv0);
        *(uint32_t*)(yf + (size_t)(tok0 + 8) * C_ + d) = pack_f16(o[nf][2] * inv1, o[nf][3] * inv1);
    }
}

// ---------------------------------------------------------------------------
extern "C" void kernel_launch(void* const* d_in, const int* in_sizes, int n_in,
                              void* d_out, int out_size)
{
    const float* x      = (const float*)d_in[0];
    const float* W_attn = (const float*)d_in[1];
    const float* b_attn = (const float*)d_in[2];
    const float* W_proj = (const float*)d_in[3];
    const float* b_proj = (const float*)d_in[4];
    float* out = (float*)d_out;

    __half *xf, *wtf, *wptf, *yf, *qpf, *kpf, *vtf;
    cudaGetSymbolAddress((void**)&xf,   g_xf);
    cudaGetSymbolAddress((void**)&wtf,  g_wtf);
    cudaGetSymbolAddress((void**)&wptf, g_wptf);
    cudaGetSymbolAddress((void**)&yf,   g_yf);
    cudaGetSymbolAddress((void**)&qpf,  g_qpf);
    cudaGetSymbolAddress((void**)&kpf,  g_kpf);
    cudaGetSymbolAddress((void**)&vtf,  g_vtf);

    cudaFuncSetAttribute(gemm_mma_kernel<0>,
                         cudaFuncAttributeMaxDynamicSharedMemorySize, GEMM_SMEM);
    cudaFuncSetAttribute(gemm_mma_kernel<1>,
                         cudaFuncAttributeMaxDynamicSharedMemorySize, GEMM_SMEM);
    cudaFuncSetAttribute(attn_mma_kernel,
                         cudaFuncAttributeMaxDynamicSharedMemorySize, ATTN_SMEM);

    // 1) conversions (single fp16)
    convert_f16<<<(M_ * C_) / 1024, 256>>>(x, xf, M_ * C_);
    transpose_convert_f16<<<dim3(3 * C_ / 32, C_ / 32), 256>>>(W_attn, wtf, C_, 3 * C_);
    transpose_convert_f16<<<dim3(C_ / 32, C_ / 32), 256>>>(W_proj, wptf, C_, C_);

    // 2) qkv GEMM with fully fused epilogue: q/k prepack + v transposed fp16
    gemm_mma_kernel<1><<<dim3(3 * C_ / 128, M_ / 128), 256, GEMM_SMEM>>>(
        xf, wtf, b_attn, nullptr, qpf, kpf, vtf, M_, 3 * C_, C_);

    // 3) fp16 flash attention (3-stage) -> yf
    attn_mma_kernel<<<dim3(T_ / 128, NH_, B_), 256, ATTN_SMEM>>>(qpf, kpf, vtf, yf);

    // 4) out = y @ W_proj + b_proj
    gemm_mma_kernel<0><<<dim3(C_ / 128, M_ / 128), 256, GEMM_SMEM>>>(
        yf, wptf, b_proj, out, nullptr, nullptr, nullptr, M_, C_, C_);
}